// round 14
// baseline (speedup 1.0000x reference)
#include <cuda_runtime.h>
#include <cuda_bf16.h>
#include <cstdint>

// Problem constants
#define B_  2
#define T_  2048
#define D_  1024
#define H_  16
#define DH_ 64
#define TOPK_ 32
#define BH_ (B_*H_)

// Packed fp32x2 FMA
#define FMA_F32X2(d, a, b, c) \
    asm("fma.rn.f32x2 %0, %1, %2, %3;" : "=l"(d) : "l"(a), "l"(b), "l"(c))
#define PACK_DUP_F32X2(out, v) \
    asm("mov.b64 %0, {%1, %1};" : "=l"(out) : "r"(__float_as_uint(v)))
#define UNPACK_F32X2_(lo, hi, in) \
    asm("mov.b64 {%0, %1}, %2;" : "=r"(lo), "=r"(hi) : "l"(in))

__device__ __forceinline__ uint32_t smem_u32(const void* p) {
    uint32_t a;
    asm("{ .reg .u64 t; cvta.to.shared.u64 t, %1; cvt.u32.u64 %0, t; }" : "=r"(a) : "l"(p));
    return a;
}
__device__ __forceinline__ void ldsm_x4(unsigned r[4], uint32_t addr) {
    asm volatile("ldmatrix.sync.aligned.m8n8.x4.shared.b16 {%0,%1,%2,%3}, [%4];"
        : "=r"(r[0]), "=r"(r[1]), "=r"(r[2]), "=r"(r[3]) : "r"(addr));
}
__device__ __forceinline__ void ldsm_x2(unsigned r[2], uint32_t addr) {
    asm volatile("ldmatrix.sync.aligned.m8n8.x2.shared.b16 {%0,%1}, [%2];"
        : "=r"(r[0]), "=r"(r[1]) : "r"(addr));
}
__device__ __forceinline__ void mma_bf16(float d[4], const unsigned a[4], const unsigned b[2]) {
    asm volatile("mma.sync.aligned.m16n8k16.row.col.f32.bf16.bf16.f32 "
        "{%0,%1,%2,%3}, {%4,%5,%6,%7}, {%8,%9}, {%0,%1,%2,%3};"
        : "+f"(d[0]), "+f"(d[1]), "+f"(d[2]), "+f"(d[3])
        : "r"(a[0]), "r"(a[1]), "r"(a[2]), "r"(a[3]), "r"(b[0]), "r"(b[1]));
}
__device__ __forceinline__ uint32_t stoff(int r, int g) {
    return (uint32_t)(r * 64 + ((g ^ ((r >> 1) & 3)) << 4));
}

// ---------------------------------------------------------------------------
// Scratch
// ---------------------------------------------------------------------------
__device__ __align__(16) float g_Q[(size_t)BH_ * T_ * DH_];
__device__ __align__(16) float g_K[(size_t)BH_ * T_ * DH_];
__device__ __align__(16) float g_V[(size_t)BH_ * T_ * DH_];
__device__ __align__(16) __nv_bfloat16 g_Sb[(size_t)BH_ * T_ * T_];   // approx scores
__device__ __align__(16) float g_AO[(size_t)B_ * T_ * D_];
__device__ __align__(16) __nv_bfloat16 g_Xs [(size_t)4096 * 3072];  // (h,h,l)
__device__ __align__(16) __nv_bfloat16 g_AOs[(size_t)4096 * 3072];  // (h,h,l)
__device__ __align__(16) __nv_bfloat16 g_Wvs[(size_t)1024 * 3072];  // (h,l,h)
__device__ __align__(16) __nv_bfloat16 g_Wos[(size_t)1024 * 3072];  // (h,l,h)
__device__ __align__(16) __nv_bfloat16 g_Qs3[(size_t)BH_ * T_ * 192];
__device__ __align__(16) __nv_bfloat16 g_Ks3[(size_t)BH_ * T_ * 192];

// ---------------------------------------------------------------------------
// Split: fp32 [R,1024] -> bf16 [R,3072]; AHL=1 (h,h,l), AHL=0 (h,l,h)
// ---------------------------------------------------------------------------
template<int AHL>
__global__ __launch_bounds__(256)
void split_bf16(const float* __restrict__ in, __nv_bfloat16* __restrict__ outp)
{
    const int idx = blockIdx.x * 256 + threadIdx.x;
    const int r = idx >> 8;
    const int c = (idx & 255) * 4;
    float4 v = *(const float4*)(in + (size_t)r * 1024 + c);
    __nv_bfloat162 h01 = __floats2bfloat162_rn(v.x, v.y);
    __nv_bfloat162 h23 = __floats2bfloat162_rn(v.z, v.w);
    float lx = v.x - __bfloat162float(h01.x);
    float ly = v.y - __bfloat162float(h01.y);
    float lz = v.z - __bfloat162float(h23.x);
    float lw = v.w - __bfloat162float(h23.y);
    __nv_bfloat162 l01 = __floats2bfloat162_rn(lx, ly);
    __nv_bfloat162 l23 = __floats2bfloat162_rn(lz, lw);
    __nv_bfloat162* o0 = (__nv_bfloat162*)(outp + (size_t)r * 3072 + c);
    __nv_bfloat162* o1 = (__nv_bfloat162*)(outp + (size_t)r * 3072 + 1024 + c);
    __nv_bfloat162* o2 = (__nv_bfloat162*)(outp + (size_t)r * 3072 + 2048 + c);
    o0[0] = h01; o0[1] = h23;
    if (AHL) { o1[0] = h01; o1[1] = h23; o2[0] = l01; o2[1] = l23; }
    else     { o1[0] = l01; o1[1] = l23; o2[0] = h01; o2[1] = h23; }
}

// Split Q/K: fp32 [R,64] -> bf16 [R,192]; AHL=1 (h,h,l), AHL=0 (h,l,h)
template<int AHL>
__global__ __launch_bounds__(256)
void split_qk3(const float* __restrict__ in, __nv_bfloat16* __restrict__ outp)
{
    const int idx = blockIdx.x * 256 + threadIdx.x;
    const int r = idx >> 4;
    const int c = (idx & 15) * 4;
    float4 v = *(const float4*)(in + (size_t)r * 64 + c);
    __nv_bfloat162 h01 = __floats2bfloat162_rn(v.x, v.y);
    __nv_bfloat162 h23 = __floats2bfloat162_rn(v.z, v.w);
    float lx = v.x - __bfloat162float(h01.x);
    float ly = v.y - __bfloat162float(h01.y);
    float lz = v.z - __bfloat162float(h23.x);
    float lw = v.w - __bfloat162float(h23.y);
    __nv_bfloat162 l01 = __floats2bfloat162_rn(lx, ly);
    __nv_bfloat162 l23 = __floats2bfloat162_rn(lz, lw);
    __nv_bfloat162* o0 = (__nv_bfloat162*)(outp + (size_t)r * 192 + c);
    __nv_bfloat162* o1 = (__nv_bfloat162*)(outp + (size_t)r * 192 + 64 + c);
    __nv_bfloat162* o2 = (__nv_bfloat162*)(outp + (size_t)r * 192 + 128 + c);
    o0[0] = h01; o0[1] = h23;
    if (AHL) { o1[0] = h01; o1[1] = h23; o2[0] = l01; o2[1] = l23; }
    else     { o1[0] = l01; o1[1] = l23; o2[0] = h01; o2[1] = h23; }
}

// ---------------------------------------------------------------------------
// HMMA bf16 GEMM, register-staged prefetch (LDG early, STS after compute).
// EPI 0: head-split fp32 [BH,T,DH] (N==1024)
// EPI 1: +bias fp32 plain [M,1024]
// EPI 2: *0.125 -> bf16 plain [M,N]
// ---------------------------------------------------------------------------
template<int EPI>
__global__ __launch_bounds__(256, 2)
void gemm_bf16_mma(const __nv_bfloat16* __restrict__ Ag,
                   const __nv_bfloat16* __restrict__ Bg,
                   const float* __restrict__ bias, void* __restrict__ Cv,
                   int N, int K, long sA, long sB, long sC)
{
    const int NC = K >> 5;
    constexpr uint32_t TILE = 128 * 64;
    __shared__ __align__(128) char sm[2][2][TILE];

    const __nv_bfloat16* A = Ag + (size_t)blockIdx.z * sA;
    const __nv_bfloat16* Bm = Bg + (size_t)blockIdx.z * sB;

    const int tid = threadIdx.x, lane = tid & 31, wid = tid >> 5;
    const int wr = wid >> 2, wc = wid & 3;
    const int m0 = blockIdx.y * 128, n0 = blockIdx.x * 128;
    const uint32_t sbase = smem_u32(&sm[0][0][0]);

    float acc[4][4][4];
#pragma unroll
    for (int mb = 0; mb < 4; mb++)
#pragma unroll
        for (int nb = 0; nb < 4; nb++)
#pragma unroll
            for (int e = 0; e < 4; e++) acc[mb][nb][e] = 0.f;

    const int aRow = (lane & 15), aG = (lane >> 4) & 1;
    const int bRow = (lane & 7),  bG = (lane >> 3) & 1;

    // per-thread load coordinates
    const int lr0 = (tid * 2) >> 2,      lg0 = (tid * 2) & 3;
    const int lr1 = (tid * 2 + 1) >> 2,  lg1 = (tid * 2 + 1) & 3;

    // prologue: chunk 0 -> buf 0 (synchronous)
    {
        *(uint4*)(&sm[0][0][0] + stoff(lr0, lg0)) = *(const uint4*)(A  + (size_t)(m0 + lr0) * K + lg0 * 8);
        *(uint4*)(&sm[0][0][0] + stoff(lr1, lg1)) = *(const uint4*)(A  + (size_t)(m0 + lr1) * K + lg1 * 8);
        *(uint4*)(&sm[0][1][0] + stoff(lr0, lg0)) = *(const uint4*)(Bm + (size_t)(n0 + lr0) * K + lg0 * 8);
        *(uint4*)(&sm[0][1][0] + stoff(lr1, lg1)) = *(const uint4*)(Bm + (size_t)(n0 + lr1) * K + lg1 * 8);
    }
    __syncthreads();

    for (int c = 0; c < NC; c++) {
        const int buf = c & 1;
        // 1) issue next-chunk LDGs into registers (no STS yet -> no stall here)
        uint4 va0, va1, vb0, vb1;
        const bool pf = (c + 1 < NC);
        if (pf) {
            const int ks = (c + 1) * 32;
            va0 = *(const uint4*)(A  + (size_t)(m0 + lr0) * K + ks + lg0 * 8);
            va1 = *(const uint4*)(A  + (size_t)(m0 + lr1) * K + ks + lg1 * 8);
            vb0 = *(const uint4*)(Bm + (size_t)(n0 + lr0) * K + ks + lg0 * 8);
            vb1 = *(const uint4*)(Bm + (size_t)(n0 + lr1) * K + ks + lg1 * 8);
        }
        // 2) compute on current buffer (hides the LDG latency)
        const uint32_t Ab = sbase + (uint32_t)buf * (2 * TILE);
        const uint32_t Bb = Ab + TILE;
#pragma unroll
        for (int s16 = 0; s16 < 2; s16++) {
            unsigned bfr[4][2];
#pragma unroll
            for (int nb = 0; nb < 4; nb++) {
                int r = 32 * wc + 8 * nb + bRow;
                ldsm_x2(bfr[nb], Bb + stoff(r, s16 * 2 + bG));
            }
#pragma unroll
            for (int mb = 0; mb < 4; mb++) {
                unsigned af[4];
                int r = 64 * wr + 16 * mb + aRow;
                ldsm_x4(af, Ab + stoff(r, s16 * 2 + aG));
#pragma unroll
                for (int nb = 0; nb < 4; nb++)
                    mma_bf16(acc[mb][nb], af, bfr[nb]);
            }
        }
        // 3) stage prefetched data into the other buffer
        if (pf) {
            const int nb_ = buf ^ 1;
            *(uint4*)(&sm[nb_][0][0] + stoff(lr0, lg0)) = va0;
            *(uint4*)(&sm[nb_][0][0] + stoff(lr1, lg1)) = va1;
            *(uint4*)(&sm[nb_][1][0] + stoff(lr0, lg0)) = vb0;
            *(uint4*)(&sm[nb_][1][0] + stoff(lr1, lg1)) = vb1;
        }
        __syncthreads();
    }

#pragma unroll
    for (int mb = 0; mb < 4; mb++) {
        const int mlo = m0 + 64 * wr + 16 * mb + (lane >> 2);
#pragma unroll
        for (int nb = 0; nb < 4; nb++) {
            const int n = n0 + 32 * wc + 8 * nb + (lane & 3) * 2;
            float2 lo = make_float2(acc[mb][nb][0], acc[mb][nb][1]);
            float2 hi = make_float2(acc[mb][nb][2], acc[mb][nb][3]);
            if (EPI == 1) {
                float* C = (float*)Cv;
                float bx = bias[n], by = bias[n + 1];
                lo.x += bx; lo.y += by; hi.x += bx; hi.y += by;
                *(float2*)(C + (size_t)mlo * N + n) = lo;
                *(float2*)(C + (size_t)(mlo + 8) * N + n) = hi;
            } else if (EPI == 2) {
                __nv_bfloat16* C = (__nv_bfloat16*)Cv + (size_t)blockIdx.z * sC;
                __nv_bfloat162 p0 = __floats2bfloat162_rn(lo.x * 0.125f, lo.y * 0.125f);
                __nv_bfloat162 p1 = __floats2bfloat162_rn(hi.x * 0.125f, hi.y * 0.125f);
                *(__nv_bfloat162*)(C + (size_t)mlo * N + n) = p0;
                *(__nv_bfloat162*)(C + (size_t)(mlo + 8) * N + n) = p1;
            } else {
                float* C = (float*)Cv;
                const int h = n >> 6, inner = n & 63;
                const int bb0 = mlo >> 11, t0v = mlo & (T_ - 1);
                const int bb1 = (mlo + 8) >> 11, t1v = (mlo + 8) & (T_ - 1);
                *(float2*)(C + (((size_t)(bb0 * H_ + h) * T_ + t0v) * DH_ + inner)) = lo;
                *(float2*)(C + (((size_t)(bb1 * H_ + h) * T_ + t1v) * DH_ + inner)) = hi;
            }
        }
    }
}

// ---------------------------------------------------------------------------
// SIMT FFMA2 GEMM — Q, K projections (selection-critical, bit-identical R8)
// ---------------------------------------------------------------------------
__global__ __launch_bounds__(256)
void gemm_abt_heads(const float* __restrict__ A, const float* __restrict__ Bm,
                    float* __restrict__ C, int M, int N, int K)
{
    __shared__ __align__(16) float AsT[16][128];
    __shared__ __align__(16) float BsT[16][128];

    const int tid = threadIdx.x;
    const int tx = tid & 15;
    const int ty = tid >> 4;
    const int m0 = blockIdx.y * 128;
    const int n0 = blockIdx.x * 128;

    unsigned long long acc2[8][4];
#pragma unroll
    for (int i = 0; i < 8; i++)
#pragma unroll
        for (int j = 0; j < 4; j++) acc2[i][j] = 0ull;

    for (int k0 = 0; k0 < K; k0 += 16) {
#pragma unroll
        for (int i = 0; i < 2; i++) {
            int idx  = tid * 2 + i;
            int row  = idx >> 2;
            int col4 = (idx & 3) * 4;
            float4 va = *(const float4*)(A + (long)(m0 + row) * K + k0 + col4);
            AsT[col4 + 0][row] = va.x;
            AsT[col4 + 1][row] = va.y;
            AsT[col4 + 2][row] = va.z;
            AsT[col4 + 3][row] = va.w;
            float4 vb = *(const float4*)(Bm + (long)(n0 + row) * K + k0 + col4);
            BsT[col4 + 0][row] = vb.x;
            BsT[col4 + 1][row] = vb.y;
            BsT[col4 + 2][row] = vb.z;
            BsT[col4 + 3][row] = vb.w;
        }
        __syncthreads();
#pragma unroll
        for (int k = 0; k < 16; k++) {
            float a[8];
            *(float4*)&a[0] = *(const float4*)&AsT[k][ty * 8];
            *(float4*)&a[4] = *(const float4*)&AsT[k][ty * 8 + 4];
            ulonglong2 b01 = *(const ulonglong2*)&BsT[k][tx * 8];
            ulonglong2 b23 = *(const ulonglong2*)&BsT[k][tx * 8 + 4];
#pragma unroll
            for (int i = 0; i < 8; i++) {
                unsigned long long ad;
                PACK_DUP_F32X2(ad, a[i]);
                FMA_F32X2(acc2[i][0], ad, b01.x, acc2[i][0]);
                FMA_F32X2(acc2[i][1], ad, b01.y, acc2[i][1]);
                FMA_F32X2(acc2[i][2], ad, b23.x, acc2[i][2]);
                FMA_F32X2(acc2[i][3], ad, b23.y, acc2[i][3]);
            }
        }
        __syncthreads();
    }

#pragma unroll
    for (int i = 0; i < 8; i++) {
        int m = m0 + ty * 8 + i;
#pragma unroll
        for (int jp = 0; jp < 4; jp += 2) {
            int n = n0 + tx * 8 + jp * 2;
            unsigned r0, r1, r2, r3;
            UNPACK_F32X2_(r0, r1, acc2[i][jp]);
            UNPACK_F32X2_(r2, r3, acc2[i][jp + 1]);
            float4 r = make_float4(__uint_as_float(r0), __uint_as_float(r1),
                                   __uint_as_float(r2), __uint_as_float(r3));
            int bb = m >> 11, t = m & (T_ - 1);
            int h = n >> 6, inner = n & (DH_ - 1);
            float* dst = C + (((long)(bb * H_ + h) * T_ + t) * DH_ + inner);
            *(float4*)dst = r;
        }
    }
}

// ---------------------------------------------------------------------------
// Approx-select (16-bit radix on bf16 scores) + exact fp32 re-rank +
// softmax + sparse AV. One block (128 threads) per query row.
// ---------------------------------------------------------------------------
__device__ __forceinline__ int enc16(int b) {
    return (b & 0x8000) ? (~b & 0xFFFF) : (b | 0x8000);
}
__device__ __forceinline__ float dec16f(int u) {
    int b = (u & 0x8000) ? (u & 0x7FFF) : (~u & 0xFFFF);
    return __uint_as_float((unsigned)b << 16);
}

__global__ __launch_bounds__(128)
void topk_rerank_av(const __nv_bfloat16* __restrict__ S,
                    const float* __restrict__ Qf, const float* __restrict__ Kf,
                    const float* __restrict__ V, float* __restrict__ O,
                    int bh_base)
{
    __shared__ int      hist[256];
    __shared__ float    s_q[64];
    __shared__ int      s_list[128];
    __shared__ float    s_v[128];
    __shared__ float    s_p[128];
    __shared__ float    s_part[128];
    __shared__ int      s_prefix;
    __shared__ int      s_kp;
    __shared__ int      s_cnt;
    __shared__ float    s_inv;

    const long row = blockIdx.x;
    const int bhl = (int)(row >> 11);
    const int bh = bh_base + bhl;
    const int tq = (int)(row & (T_ - 1));
    const int tid = threadIdx.x;

    if (tid == 0) s_cnt = 0;
    if (tid < 16)
        *(float4*)&s_q[tid * 4] =
            *(const float4*)(Qf + (((size_t)bhl * T_ + tq) * DH_) + tid * 4);

    // load 16 bf16 approx scores per thread (2 x uint4, coalesced)
    const uint4* S4 = (const uint4*)(S + row * T_);
    int us[16];
    int ibase[2];
#pragma unroll
    for (int i = 0; i < 2; i++) {
        uint4 w = S4[tid + i * 128];
        ibase[i] = (tid + i * 128) * 8;
        unsigned ws[4] = {w.x, w.y, w.z, w.w};
#pragma unroll
        for (int j = 0; j < 4; j++) {
            us[i * 8 + j * 2 + 0] = enc16((int)(ws[j] & 0xFFFFu));
            us[i * 8 + j * 2 + 1] = enc16((int)(ws[j] >> 16));
        }
    }

    // 2-level radix select (exact kth largest of bf16 values, k=32)
    int prefix = 0, kprime = TOPK_;
#pragma unroll
    for (int level = 1; level >= 0; --level) {
        const int sh = level * 8;
        hist[tid] = 0;
        hist[tid + 128] = 0;
        __syncthreads();
        const int hip = prefix >> (sh + 8);
#pragma unroll
        for (int i = 0; i < 16; i++) {
            int u = us[i];
            if ((u >> (sh + 8)) == hip)
                atomicAdd(&hist[(u >> sh) & 0xFF], 1);
        }
        __syncthreads();
        if (tid < 32) {
            const int base = tid * 8;
            int s = 0;
#pragma unroll
            for (int j = 0; j < 8; j++) s += hist[base + j];
            int suf = s;
#pragma unroll
            for (int off = 1; off < 32; off <<= 1) {
                int o = __shfl_down_sync(0xffffffffu, suf, off);
                if (tid + off < 32) suf += o;
            }
            int sufnext = __shfl_down_sync(0xffffffffu, suf, 1);
            if (tid == 31) sufnext = 0;
            unsigned mk = __ballot_sync(0xffffffffu, suf >= kprime);
            int lsel = 31 - __clz(mk);
            if (tid == lsel) {
                int running = sufnext;
                int b = base + 7;
                for (; b >= base; --b) {
                    int h = hist[b];
                    if (running + h >= kprime) break;
                    running += h;
                }
                s_prefix = prefix | (b << sh);
                s_kp = kprime - running;
            }
        }
        __syncthreads();
        prefix = s_prefix;
        kprime = s_kp;
    }

    // widened acceptance threshold (margin covers approx error soundly)
    const float thrf = dec16f(prefix) - 0.05f;
    const int uthr_w = enc16((int)(__bfloat16_as_ushort(__float2bfloat16(thrf))));

    // compact candidates
#pragma unroll
    for (int i = 0; i < 16; i++) {
        if (us[i] >= uthr_w) {
            int pos = atomicAdd(&s_cnt, 1);
            if (pos < 128)
                s_list[pos] = ibase[i >> 3] + (i & 7);
        }
    }
    __syncthreads();
    const int cnt = min(s_cnt, 128);

    // exact fp32 recompute for candidates
    if (tid < cnt) {
        const float* Kr = Kf + ((size_t)bhl * T_ + s_list[tid]) * DH_;
        float acc = 0.f;
#pragma unroll
        for (int k4 = 0; k4 < 16; k4++) {
            float4 kv = *(const float4*)(Kr + k4 * 4);
            acc = fmaf(s_q[k4 * 4 + 0], kv.x, acc);
            acc = fmaf(s_q[k4 * 4 + 1], kv.y, acc);
            acc = fmaf(s_q[k4 * 4 + 2], kv.z, acc);
            acc = fmaf(s_q[k4 * 4 + 3], kv.w, acc);
        }
        s_v[tid] = acc * 0.125f;
    }
    __syncthreads();

    // exact rank among candidates; keep rank<32 (ties kept, matching ref)
    float m = -3.4e38f;
    for (int j = 0; j < cnt; j++) m = fmaxf(m, s_v[j]);
    if (tid < cnt) {
        const float v = s_v[tid];
        int c = 0;
        for (int j = 0; j < cnt; j++) c += (s_v[j] > v);
        s_p[tid] = (c < TOPK_) ? __expf(v - m) : 0.f;
    }
    __syncthreads();

    // softmax denominator (warp 0)
    if (tid < 32) {
        float sum = 0.f;
        for (int e = tid; e < cnt; e += 32) sum += s_p[e];
#pragma unroll
        for (int off = 16; off; off >>= 1)
            sum += __shfl_xor_sync(0xffffffffu, sum, off);
        if (tid == 0) s_inv = 1.f / sum;
    }
    __syncthreads();

    // sparse P @ V
    {
        const int dim = tid & 63;
        const int half = tid >> 6;
        const float* Vb = V + (size_t)bhl * T_ * DH_;
        float acc = 0.f;
        for (int e = half; e < cnt; e += 2)
            acc += s_p[e] * Vb[(size_t)s_list[e] * DH_ + dim];
        s_part[tid] = acc;
    }
    __syncthreads();
    if (tid < DH_) {
        const int bb = bh >> 4, h = bh & (H_ - 1);
        float o = (s_part[tid] + s_part[tid + 64]) * s_inv;
        O[((size_t)(bb * T_ + tq)) * D_ + h * DH_ + tid] = o;
    }
}

// ---------------------------------------------------------------------------
// Launch
// ---------------------------------------------------------------------------
#define NCHUNK 4
#define BH_PER (BH_ / NCHUNK)   // 8

extern "C" void kernel_launch(void* const* d_in, const int* in_sizes, int n_in,
                              void* d_out, int out_size)
{
    const float* x    = (const float*)d_in[0];
    const float* Wq   = (const float*)d_in[1];
    const float* Wk   = (const float*)d_in[2];
    const float* Wv   = (const float*)d_in[3];
    const float* Wo_w = (const float*)d_in[4];
    const float* Wo_b = (const float*)d_in[5];
    float* out = (float*)d_out;

    float *pQ, *pK, *pV, *pAO;
    __nv_bfloat16 *pSb, *pXs, *pAOs, *pWvs, *pWos, *pQs3, *pKs3;
    cudaGetSymbolAddress((void**)&pQ,   g_Q);
    cudaGetSymbolAddress((void**)&pK,   g_K);
    cudaGetSymbolAddress((void**)&pV,   g_V);
    cudaGetSymbolAddress((void**)&pSb,  g_Sb);
    cudaGetSymbolAddress((void**)&pAO,  g_AO);
    cudaGetSymbolAddress((void**)&pXs,  g_Xs);
    cudaGetSymbolAddress((void**)&pAOs, g_AOs);
    cudaGetSymbolAddress((void**)&pWvs, g_Wvs);
    cudaGetSymbolAddress((void**)&pWos, g_Wos);
    cudaGetSymbolAddress((void**)&pQs3, g_Qs3);
    cudaGetSymbolAddress((void**)&pKs3, g_Ks3);

    static cudaStream_t sB = nullptr, sC = nullptr;
    static cudaEvent_t e0, eV, eS[NCHUNK], eT;
    if (!sB) {
        cudaStreamCreateWithFlags(&sB, cudaStreamNonBlocking);
        cudaStreamCreateWithFlags(&sC, cudaStreamNonBlocking);
        cudaEventCreateWithFlags(&e0, cudaEventDisableTiming);
        cudaEventCreateWithFlags(&eV, cudaEventDisableTiming);
        for (int i = 0; i < NCHUNK; i++)
            cudaEventCreateWithFlags(&eS[i], cudaEventDisableTiming);
        cudaEventCreateWithFlags(&eT, cudaEventDisableTiming);
    }

    const int M = B_ * T_;   // 4096

    cudaEventRecord(e0, 0);
    cudaStreamWaitEvent(sB, e0, 0);

    // Stream B: splits + V projection (tensor pipe)
    split_bf16<1><<<4096, 256, 0, sB>>>(x, pXs);
    split_bf16<0><<<1024, 256, 0, sB>>>(Wv, pWvs);
    split_bf16<0><<<1024, 256, 0, sB>>>(Wo_w, pWos);
    {
        dim3 grid(D_ / 128, M / 128, 1);
        gemm_bf16_mma<0><<<grid, 256, 0, sB>>>(pXs, pWvs, nullptr, pV, D_, 3072, 0, 0, 0);
    }
    cudaEventRecord(eV, sB);

    // Main stream: Q, K projections (fp32 FFMA2, selection-critical)
    {
        dim3 grid(D_ / 128, M / 128, 1);
        gemm_abt_heads<<<grid, 256>>>(x, Wq, pQ, M, D_, D_);
        gemm_abt_heads<<<grid, 256>>>(x, Wk, pK, M, D_, D_);
    }
    // 3-term splits of Q, K for approx scores
    split_qk3<1><<<4096, 256>>>(pQ, pQs3);
    split_qk3<0><<<4096, 256>>>(pK, pKs3);

    // Approx scores (bf16 HMMA) chunked; rerank-topk chunk i overlaps chunk i+1
    cudaStreamWaitEvent(sC, eV, 0);
    for (int c = 0; c < NCHUNK; c++) {
        const long boff = (long)c * BH_PER;
        dim3 grid(T_ / 128, T_ / 128, BH_PER);
        gemm_bf16_mma<2><<<grid, 256>>>(pQs3 + boff * T_ * 192,
                                        pKs3 + boff * T_ * 192,
                                        nullptr, pSb + boff * T_ * T_,
                                        T_, 192,
                                        (long)T_ * 192, (long)T_ * 192,
                                        (long)T_ * T_);
        cudaEventRecord(eS[c], 0);
        cudaStreamWaitEvent(sC, eS[c], 0);
        topk_rerank_av<<<BH_PER * T_, 128, 0, sC>>>(pSb + boff * T_ * T_,
                                                    pQ + boff * T_ * DH_,
                                                    pK + boff * T_ * DH_,
                                                    pV + boff * T_ * DH_,
                                                    pAO, (int)boff);
    }
    cudaEventRecord(eT, sC);
    cudaStreamWaitEvent(0, eT, 0);

    // Output projection (HMMA 3-term + bias)
    split_bf16<1><<<4096, 256>>>(pAO, pAOs);
    {
        dim3 grid(D_ / 128, M / 128, 1);
        gemm_bf16_mma<1><<<grid, 256>>>(pAOs, pWos, Wo_b, out, D_, 3072, 0, 0, 0);
    }
}

// round 15
// speedup vs baseline: 1.0583x; 1.0583x over previous
#include <cuda_runtime.h>
#include <cuda_bf16.h>
#include <cstdint>

// Problem constants
#define B_  2
#define T_  2048
#define D_  1024
#define H_  16
#define DH_ 64
#define TOPK_ 32
#define BH_ (B_*H_)

// Packed fp32x2 FMA
#define FMA_F32X2(d, a, b, c) \
    asm("fma.rn.f32x2 %0, %1, %2, %3;" : "=l"(d) : "l"(a), "l"(b), "l"(c))
#define PACK_DUP_F32X2(out, v) \
    asm("mov.b64 %0, {%1, %1};" : "=l"(out) : "r"(__float_as_uint(v)))
#define UNPACK_F32X2_(lo, hi, in) \
    asm("mov.b64 {%0, %1}, %2;" : "=r"(lo), "=r"(hi) : "l"(in))

__device__ __forceinline__ uint32_t smem_u32(const void* p) {
    uint32_t a;
    asm("{ .reg .u64 t; cvta.to.shared.u64 t, %1; cvt.u32.u64 %0, t; }" : "=r"(a) : "l"(p));
    return a;
}
__device__ __forceinline__ void ldsm_x4(unsigned r[4], uint32_t addr) {
    asm volatile("ldmatrix.sync.aligned.m8n8.x4.shared.b16 {%0,%1,%2,%3}, [%4];"
        : "=r"(r[0]), "=r"(r[1]), "=r"(r[2]), "=r"(r[3]) : "r"(addr));
}
__device__ __forceinline__ void ldsm_x2(unsigned r[2], uint32_t addr) {
    asm volatile("ldmatrix.sync.aligned.m8n8.x2.shared.b16 {%0,%1}, [%2];"
        : "=r"(r[0]), "=r"(r[1]) : "r"(addr));
}
__device__ __forceinline__ void mma_bf16(float d[4], const unsigned a[4], const unsigned b[2]) {
    asm volatile("mma.sync.aligned.m16n8k16.row.col.f32.bf16.bf16.f32 "
        "{%0,%1,%2,%3}, {%4,%5,%6,%7}, {%8,%9}, {%0,%1,%2,%3};"
        : "+f"(d[0]), "+f"(d[1]), "+f"(d[2]), "+f"(d[3])
        : "r"(a[0]), "r"(a[1]), "r"(a[2]), "r"(a[3]), "r"(b[0]), "r"(b[1]));
}
__device__ __forceinline__ uint32_t stoff(int r, int g) {
    return (uint32_t)(r * 64 + ((g ^ ((r >> 1) & 3)) << 4));
}

// ---------------------------------------------------------------------------
// Scratch
// ---------------------------------------------------------------------------
__device__ __align__(16) float g_Q[(size_t)BH_ * T_ * DH_];
__device__ __align__(16) float g_K[(size_t)BH_ * T_ * DH_];
__device__ __align__(16) float g_V[(size_t)BH_ * T_ * DH_];
__device__ __align__(16) __nv_bfloat16 g_Sb[(size_t)BH_ * T_ * T_];   // approx scores
__device__ __align__(16) float g_AO[(size_t)B_ * T_ * D_];
__device__ __align__(16) __nv_bfloat16 g_Xs [(size_t)4096 * 3072];  // (h,h,l)
__device__ __align__(16) __nv_bfloat16 g_AOs[(size_t)4096 * 3072];  // (h,h,l)
__device__ __align__(16) __nv_bfloat16 g_Wvs[(size_t)1024 * 3072];  // (h,l,h)
__device__ __align__(16) __nv_bfloat16 g_Wos[(size_t)1024 * 3072];  // (h,l,h)
__device__ __align__(16) __nv_bfloat16 g_Qb [(size_t)BH_ * T_ * 64];   // bf16 Q
__device__ __align__(16) __nv_bfloat16 g_Kb [(size_t)BH_ * T_ * 64];   // bf16 K

// ---------------------------------------------------------------------------
// Split: fp32 [R,1024] -> bf16 [R,3072]; AHL=1 (h,h,l), AHL=0 (h,l,h)
// ---------------------------------------------------------------------------
template<int AHL>
__global__ __launch_bounds__(256)
void split_bf16(const float* __restrict__ in, __nv_bfloat16* __restrict__ outp)
{
    const int idx = blockIdx.x * 256 + threadIdx.x;
    const int r = idx >> 8;
    const int c = (idx & 255) * 4;
    float4 v = *(const float4*)(in + (size_t)r * 1024 + c);
    __nv_bfloat162 h01 = __floats2bfloat162_rn(v.x, v.y);
    __nv_bfloat162 h23 = __floats2bfloat162_rn(v.z, v.w);
    float lx = v.x - __bfloat162float(h01.x);
    float ly = v.y - __bfloat162float(h01.y);
    float lz = v.z - __bfloat162float(h23.x);
    float lw = v.w - __bfloat162float(h23.y);
    __nv_bfloat162 l01 = __floats2bfloat162_rn(lx, ly);
    __nv_bfloat162 l23 = __floats2bfloat162_rn(lz, lw);
    __nv_bfloat162* o0 = (__nv_bfloat162*)(outp + (size_t)r * 3072 + c);
    __nv_bfloat162* o1 = (__nv_bfloat162*)(outp + (size_t)r * 3072 + 1024 + c);
    __nv_bfloat162* o2 = (__nv_bfloat162*)(outp + (size_t)r * 3072 + 2048 + c);
    o0[0] = h01; o0[1] = h23;
    if (AHL) { o1[0] = h01; o1[1] = h23; o2[0] = l01; o2[1] = l23; }
    else     { o1[0] = l01; o1[1] = l23; o2[0] = h01; o2[1] = h23; }
}

// Convert: fp32 [R,64] -> bf16 [R,64] (for approx scores)
__global__ __launch_bounds__(256)
void cvt_bf16_qk(const float* __restrict__ in, __nv_bfloat16* __restrict__ outp)
{
    const int idx = blockIdx.x * 256 + threadIdx.x;   // one float4 per thread
    float4 v = *(const float4*)(in + (size_t)idx * 4);
    __nv_bfloat162 p0 = __floats2bfloat162_rn(v.x, v.y);
    __nv_bfloat162 p1 = __floats2bfloat162_rn(v.z, v.w);
    __nv_bfloat162* o = (__nv_bfloat162*)(outp + (size_t)idx * 4);
    o[0] = p0; o[1] = p1;
}

// ---------------------------------------------------------------------------
// HMMA bf16 GEMM, register-staged prefetch.
// EPI 0: head-split fp32 [BH,T,DH] (N==1024)
// EPI 1: +bias fp32 plain [M,1024]
// EPI 2: *0.125 -> bf16 plain [M,N]
// ---------------------------------------------------------------------------
template<int EPI>
__global__ __launch_bounds__(256, 2)
void gemm_bf16_mma(const __nv_bfloat16* __restrict__ Ag,
                   const __nv_bfloat16* __restrict__ Bg,
                   const float* __restrict__ bias, void* __restrict__ Cv,
                   int N, int K, long sA, long sB, long sC)
{
    const int NC = K >> 5;
    constexpr uint32_t TILE = 128 * 64;
    __shared__ __align__(128) char sm[2][2][TILE];

    const __nv_bfloat16* A = Ag + (size_t)blockIdx.z * sA;
    const __nv_bfloat16* Bm = Bg + (size_t)blockIdx.z * sB;

    const int tid = threadIdx.x, lane = tid & 31, wid = tid >> 5;
    const int wr = wid >> 2, wc = wid & 3;
    const int m0 = blockIdx.y * 128, n0 = blockIdx.x * 128;
    const uint32_t sbase = smem_u32(&sm[0][0][0]);

    float acc[4][4][4];
#pragma unroll
    for (int mb = 0; mb < 4; mb++)
#pragma unroll
        for (int nb = 0; nb < 4; nb++)
#pragma unroll
            for (int e = 0; e < 4; e++) acc[mb][nb][e] = 0.f;

    const int aRow = (lane & 15), aG = (lane >> 4) & 1;
    const int bRow = (lane & 7),  bG = (lane >> 3) & 1;

    const int lr0 = (tid * 2) >> 2,      lg0 = (tid * 2) & 3;
    const int lr1 = (tid * 2 + 1) >> 2,  lg1 = (tid * 2 + 1) & 3;

    {
        *(uint4*)(&sm[0][0][0] + stoff(lr0, lg0)) = *(const uint4*)(A  + (size_t)(m0 + lr0) * K + lg0 * 8);
        *(uint4*)(&sm[0][0][0] + stoff(lr1, lg1)) = *(const uint4*)(A  + (size_t)(m0 + lr1) * K + lg1 * 8);
        *(uint4*)(&sm[0][1][0] + stoff(lr0, lg0)) = *(const uint4*)(Bm + (size_t)(n0 + lr0) * K + lg0 * 8);
        *(uint4*)(&sm[0][1][0] + stoff(lr1, lg1)) = *(const uint4*)(Bm + (size_t)(n0 + lr1) * K + lg1 * 8);
    }
    __syncthreads();

    for (int c = 0; c < NC; c++) {
        const int buf = c & 1;
        uint4 va0, va1, vb0, vb1;
        const bool pf = (c + 1 < NC);
        if (pf) {
            const int ks = (c + 1) * 32;
            va0 = *(const uint4*)(A  + (size_t)(m0 + lr0) * K + ks + lg0 * 8);
            va1 = *(const uint4*)(A  + (size_t)(m0 + lr1) * K + ks + lg1 * 8);
            vb0 = *(const uint4*)(Bm + (size_t)(n0 + lr0) * K + ks + lg0 * 8);
            vb1 = *(const uint4*)(Bm + (size_t)(n0 + lr1) * K + ks + lg1 * 8);
        }
        const uint32_t Ab = sbase + (uint32_t)buf * (2 * TILE);
        const uint32_t Bb = Ab + TILE;
#pragma unroll
        for (int s16 = 0; s16 < 2; s16++) {
            unsigned bfr[4][2];
#pragma unroll
            for (int nb = 0; nb < 4; nb++) {
                int r = 32 * wc + 8 * nb + bRow;
                ldsm_x2(bfr[nb], Bb + stoff(r, s16 * 2 + bG));
            }
#pragma unroll
            for (int mb = 0; mb < 4; mb++) {
                unsigned af[4];
                int r = 64 * wr + 16 * mb + aRow;
                ldsm_x4(af, Ab + stoff(r, s16 * 2 + aG));
#pragma unroll
                for (int nb = 0; nb < 4; nb++)
                    mma_bf16(acc[mb][nb], af, bfr[nb]);
            }
        }
        if (pf) {
            const int nb_ = buf ^ 1;
            *(uint4*)(&sm[nb_][0][0] + stoff(lr0, lg0)) = va0;
            *(uint4*)(&sm[nb_][0][0] + stoff(lr1, lg1)) = va1;
            *(uint4*)(&sm[nb_][1][0] + stoff(lr0, lg0)) = vb0;
            *(uint4*)(&sm[nb_][1][0] + stoff(lr1, lg1)) = vb1;
        }
        __syncthreads();
    }

#pragma unroll
    for (int mb = 0; mb < 4; mb++) {
        const int mlo = m0 + 64 * wr + 16 * mb + (lane >> 2);
#pragma unroll
        for (int nb = 0; nb < 4; nb++) {
            const int n = n0 + 32 * wc + 8 * nb + (lane & 3) * 2;
            float2 lo = make_float2(acc[mb][nb][0], acc[mb][nb][1]);
            float2 hi = make_float2(acc[mb][nb][2], acc[mb][nb][3]);
            if (EPI == 1) {
                float* C = (float*)Cv;
                float bx = bias[n], by = bias[n + 1];
                lo.x += bx; lo.y += by; hi.x += bx; hi.y += by;
                *(float2*)(C + (size_t)mlo * N + n) = lo;
                *(float2*)(C + (size_t)(mlo + 8) * N + n) = hi;
            } else if (EPI == 2) {
                __nv_bfloat16* C = (__nv_bfloat16*)Cv + (size_t)blockIdx.z * sC;
                __nv_bfloat162 p0 = __floats2bfloat162_rn(lo.x * 0.125f, lo.y * 0.125f);
                __nv_bfloat162 p1 = __floats2bfloat162_rn(hi.x * 0.125f, hi.y * 0.125f);
                *(__nv_bfloat162*)(C + (size_t)mlo * N + n) = p0;
                *(__nv_bfloat162*)(C + (size_t)(mlo + 8) * N + n) = p1;
            } else {
                float* C = (float*)Cv;
                const int h = n >> 6, inner = n & 63;
                const int bb0 = mlo >> 11, t0v = mlo & (T_ - 1);
                const int bb1 = (mlo + 8) >> 11, t1v = (mlo + 8) & (T_ - 1);
                *(float2*)(C + (((size_t)(bb0 * H_ + h) * T_ + t0v) * DH_ + inner)) = lo;
                *(float2*)(C + (((size_t)(bb1 * H_ + h) * T_ + t1v) * DH_ + inner)) = hi;
            }
        }
    }
}

// ---------------------------------------------------------------------------
// SIMT FFMA2 GEMM — Q, K projections (selection-critical, bit-identical R8)
// ---------------------------------------------------------------------------
__global__ __launch_bounds__(256)
void gemm_abt_heads(const float* __restrict__ A, const float* __restrict__ Bm,
                    float* __restrict__ C, int M, int N, int K)
{
    __shared__ __align__(16) float AsT[16][128];
    __shared__ __align__(16) float BsT[16][128];

    const int tid = threadIdx.x;
    const int tx = tid & 15;
    const int ty = tid >> 4;
    const int m0 = blockIdx.y * 128;
    const int n0 = blockIdx.x * 128;

    unsigned long long acc2[8][4];
#pragma unroll
    for (int i = 0; i < 8; i++)
#pragma unroll
        for (int j = 0; j < 4; j++) acc2[i][j] = 0ull;

    for (int k0 = 0; k0 < K; k0 += 16) {
#pragma unroll
        for (int i = 0; i < 2; i++) {
            int idx  = tid * 2 + i;
            int row  = idx >> 2;
            int col4 = (idx & 3) * 4;
            float4 va = *(const float4*)(A + (long)(m0 + row) * K + k0 + col4);
            AsT[col4 + 0][row] = va.x;
            AsT[col4 + 1][row] = va.y;
            AsT[col4 + 2][row] = va.z;
            AsT[col4 + 3][row] = va.w;
            float4 vb = *(const float4*)(Bm + (long)(n0 + row) * K + k0 + col4);
            BsT[col4 + 0][row] = vb.x;
            BsT[col4 + 1][row] = vb.y;
            BsT[col4 + 2][row] = vb.z;
            BsT[col4 + 3][row] = vb.w;
        }
        __syncthreads();
#pragma unroll
        for (int k = 0; k < 16; k++) {
            float a[8];
            *(float4*)&a[0] = *(const float4*)&AsT[k][ty * 8];
            *(float4*)&a[4] = *(const float4*)&AsT[k][ty * 8 + 4];
            ulonglong2 b01 = *(const ulonglong2*)&BsT[k][tx * 8];
            ulonglong2 b23 = *(const ulonglong2*)&BsT[k][tx * 8 + 4];
#pragma unroll
            for (int i = 0; i < 8; i++) {
                unsigned long long ad;
                PACK_DUP_F32X2(ad, a[i]);
                FMA_F32X2(acc2[i][0], ad, b01.x, acc2[i][0]);
                FMA_F32X2(acc2[i][1], ad, b01.y, acc2[i][1]);
                FMA_F32X2(acc2[i][2], ad, b23.x, acc2[i][2]);
                FMA_F32X2(acc2[i][3], ad, b23.y, acc2[i][3]);
            }
        }
        __syncthreads();
    }

#pragma unroll
    for (int i = 0; i < 8; i++) {
        int m = m0 + ty * 8 + i;
#pragma unroll
        for (int jp = 0; jp < 4; jp += 2) {
            int n = n0 + tx * 8 + jp * 2;
            unsigned r0, r1, r2, r3;
            UNPACK_F32X2_(r0, r1, acc2[i][jp]);
            UNPACK_F32X2_(r2, r3, acc2[i][jp + 1]);
            float4 r = make_float4(__uint_as_float(r0), __uint_as_float(r1),
                                   __uint_as_float(r2), __uint_as_float(r3));
            int bb = m >> 11, t = m & (T_ - 1);
            int h = n >> 6, inner = n & (DH_ - 1);
            float* dst = C + (((long)(bb * H_ + h) * T_ + t) * DH_ + inner);
            *(float4*)dst = r;
        }
    }
}

// ---------------------------------------------------------------------------
// Approx-select (16-bit radix on bf16 scores) + exact fp32 re-rank +
// softmax + sparse AV. One block (128 threads) per query row.
// ---------------------------------------------------------------------------
__device__ __forceinline__ int enc16(int b) {
    return (b & 0x8000) ? (~b & 0xFFFF) : (b | 0x8000);
}
__device__ __forceinline__ float dec16f(int u) {
    int b = (u & 0x8000) ? (u & 0x7FFF) : (~u & 0xFFFF);
    return __uint_as_float((unsigned)b << 16);
}

__global__ __launch_bounds__(128)
void topk_rerank_av(const __nv_bfloat16* __restrict__ S,
                    const float* __restrict__ Qf, const float* __restrict__ Kf,
                    const float* __restrict__ V, float* __restrict__ O,
                    int bh_base)
{
    __shared__ int      hist[256];
    __shared__ float    s_q[64];
    __shared__ int      s_list[128];
    __shared__ float    s_v[128];
    __shared__ float    s_p[128];
    __shared__ float    s_part[128];
    __shared__ int      s_prefix;
    __shared__ int      s_kp;
    __shared__ int      s_cnt;
    __shared__ float    s_inv;

    const long row = blockIdx.x;
    const int bhl = (int)(row >> 11);
    const int bh = bh_base + bhl;
    const int tq = (int)(row & (T_ - 1));
    const int tid = threadIdx.x;

    if (tid == 0) s_cnt = 0;
    if (tid < 16)
        *(float4*)&s_q[tid * 4] =
            *(const float4*)(Qf + (((size_t)bhl * T_ + tq) * DH_) + tid * 4);

    const uint4* S4 = (const uint4*)(S + row * T_);
    int us[16];
    int ibase[2];
#pragma unroll
    for (int i = 0; i < 2; i++) {
        uint4 w = S4[tid + i * 128];
        ibase[i] = (tid + i * 128) * 8;
        unsigned ws[4] = {w.x, w.y, w.z, w.w};
#pragma unroll
        for (int j = 0; j < 4; j++) {
            us[i * 8 + j * 2 + 0] = enc16((int)(ws[j] & 0xFFFFu));
            us[i * 8 + j * 2 + 1] = enc16((int)(ws[j] >> 16));
        }
    }

    // 2-level radix select (exact kth largest of bf16 values, k=32)
    int prefix = 0, kprime = TOPK_;
#pragma unroll
    for (int level = 1; level >= 0; --level) {
        const int sh = level * 8;
        hist[tid] = 0;
        hist[tid + 128] = 0;
        __syncthreads();
        const int hip = prefix >> (sh + 8);
#pragma unroll
        for (int i = 0; i < 16; i++) {
            int u = us[i];
            if ((u >> (sh + 8)) == hip)
                atomicAdd(&hist[(u >> sh) & 0xFF], 1);
        }
        __syncthreads();
        if (tid < 32) {
            const int base = tid * 8;
            int s = 0;
#pragma unroll
            for (int j = 0; j < 8; j++) s += hist[base + j];
            int suf = s;
#pragma unroll
            for (int off = 1; off < 32; off <<= 1) {
                int o = __shfl_down_sync(0xffffffffu, suf, off);
                if (tid + off < 32) suf += o;
            }
            int sufnext = __shfl_down_sync(0xffffffffu, suf, 1);
            if (tid == 31) sufnext = 0;
            unsigned mk = __ballot_sync(0xffffffffu, suf >= kprime);
            int lsel = 31 - __clz(mk);
            if (tid == lsel) {
                int running = sufnext;
                int b = base + 7;
                for (; b >= base; --b) {
                    int h = hist[b];
                    if (running + h >= kprime) break;
                    running += h;
                }
                s_prefix = prefix | (b << sh);
                s_kp = kprime - running;
            }
        }
        __syncthreads();
        prefix = s_prefix;
        kprime = s_kp;
    }

    // widened acceptance threshold (margin covers bf16 approx error soundly)
    const float thrf = dec16f(prefix) - 0.12f;
    const int uthr_w = enc16((int)(__bfloat16_as_ushort(__float2bfloat16(thrf))));

    // compact candidates
#pragma unroll
    for (int i = 0; i < 16; i++) {
        if (us[i] >= uthr_w) {
            int pos = atomicAdd(&s_cnt, 1);
            if (pos < 128)
                s_list[pos] = ibase[i >> 3] + (i & 7);
        }
    }
    __syncthreads();
    const int cnt = min(s_cnt, 128);

    // exact fp32 recompute for candidates
    if (tid < cnt) {
        const float* Kr = Kf + ((size_t)bhl * T_ + s_list[tid]) * DH_;
        float acc = 0.f;
#pragma unroll
        for (int k4 = 0; k4 < 16; k4++) {
            float4 kv = *(const float4*)(Kr + k4 * 4);
            acc = fmaf(s_q[k4 * 4 + 0], kv.x, acc);
            acc = fmaf(s_q[k4 * 4 + 1], kv.y, acc);
            acc = fmaf(s_q[k4 * 4 + 2], kv.z, acc);
            acc = fmaf(s_q[k4 * 4 + 3], kv.w, acc);
        }
        s_v[tid] = acc * 0.125f;
    }
    __syncthreads();

    // exact rank among candidates; keep rank<32 (ties kept, matching ref)
    float m = -3.4e38f;
    for (int j = 0; j < cnt; j++) m = fmaxf(m, s_v[j]);
    if (tid < cnt) {
        const float v = s_v[tid];
        int c = 0;
        for (int j = 0; j < cnt; j++) c += (s_v[j] > v);
        s_p[tid] = (c < TOPK_) ? __expf(v - m) : 0.f;
    }
    __syncthreads();

    if (tid < 32) {
        float sum = 0.f;
        for (int e = tid; e < cnt; e += 32) sum += s_p[e];
#pragma unroll
        for (int off = 16; off; off >>= 1)
            sum += __shfl_xor_sync(0xffffffffu, sum, off);
        if (tid == 0) s_inv = 1.f / sum;
    }
    __syncthreads();

    {
        const int dim = tid & 63;
        const int half = tid >> 6;
        const float* Vb = V + (size_t)bhl * T_ * DH_;
        float acc = 0.f;
        for (int e = half; e < cnt; e += 2)
            acc += s_p[e] * Vb[(size_t)s_list[e] * DH_ + dim];
        s_part[tid] = acc;
    }
    __syncthreads();
    if (tid < DH_) {
        const int bb = bh >> 4, h = bh & (H_ - 1);
        float o = (s_part[tid] + s_part[tid + 64]) * s_inv;
        O[((size_t)(bb * T_ + tq)) * D_ + h * DH_ + tid] = o;
    }
}

// ---------------------------------------------------------------------------
// Launch
// ---------------------------------------------------------------------------
#define NCHUNK 4
#define BH_PER (BH_ / NCHUNK)   // 8

extern "C" void kernel_launch(void* const* d_in, const int* in_sizes, int n_in,
                              void* d_out, int out_size)
{
    const float* x    = (const float*)d_in[0];
    const float* Wq   = (const float*)d_in[1];
    const float* Wk   = (const float*)d_in[2];
    const float* Wv   = (const float*)d_in[3];
    const float* Wo_w = (const float*)d_in[4];
    const float* Wo_b = (const float*)d_in[5];
    float* out = (float*)d_out;

    float *pQ, *pK, *pV, *pAO;
    __nv_bfloat16 *pSb, *pXs, *pAOs, *pWvs, *pWos, *pQb, *pKb;
    cudaGetSymbolAddress((void**)&pQ,   g_Q);
    cudaGetSymbolAddress((void**)&pK,   g_K);
    cudaGetSymbolAddress((void**)&pV,   g_V);
    cudaGetSymbolAddress((void**)&pSb,  g_Sb);
    cudaGetSymbolAddress((void**)&pAO,  g_AO);
    cudaGetSymbolAddress((void**)&pXs,  g_Xs);
    cudaGetSymbolAddress((void**)&pAOs, g_AOs);
    cudaGetSymbolAddress((void**)&pWvs, g_Wvs);
    cudaGetSymbolAddress((void**)&pWos, g_Wos);
    cudaGetSymbolAddress((void**)&pQb,  g_Qb);
    cudaGetSymbolAddress((void**)&pKb,  g_Kb);

    static cudaStream_t sB = nullptr, sC = nullptr;
    static cudaEvent_t e0, eV, eS[NCHUNK], eT;
    if (!sB) {
        cudaStreamCreateWithFlags(&sB, cudaStreamNonBlocking);
        cudaStreamCreateWithFlags(&sC, cudaStreamNonBlocking);
        cudaEventCreateWithFlags(&e0, cudaEventDisableTiming);
        cudaEventCreateWithFlags(&eV, cudaEventDisableTiming);
        for (int i = 0; i < NCHUNK; i++)
            cudaEventCreateWithFlags(&eS[i], cudaEventDisableTiming);
        cudaEventCreateWithFlags(&eT, cudaEventDisableTiming);
    }

    const int M = B_ * T_;   // 4096

    cudaEventRecord(e0, 0);
    cudaStreamWaitEvent(sB, e0, 0);

    // Stream B: splits + V projection (tensor pipe)
    split_bf16<1><<<4096, 256, 0, sB>>>(x, pXs);
    split_bf16<0><<<1024, 256, 0, sB>>>(Wv, pWvs);
    split_bf16<0><<<1024, 256, 0, sB>>>(Wo_w, pWos);
    {
        dim3 grid(D_ / 128, M / 128, 1);
        gemm_bf16_mma<0><<<grid, 256, 0, sB>>>(pXs, pWvs, nullptr, pV, D_, 3072, 0, 0, 0);
    }
    cudaEventRecord(eV, sB);

    // Main stream: Q, K projections (fp32 FFMA2, selection-critical)
    {
        dim3 grid(D_ / 128, M / 128, 1);
        gemm_abt_heads<<<grid, 256>>>(x, Wq, pQ, M, D_, D_);
        gemm_abt_heads<<<grid, 256>>>(x, Wk, pK, M, D_, D_);
    }
    // plain bf16 conversions of Q, K for approx scores (K=64)
    cvt_bf16_qk<<<4096, 256>>>(pQ, pQb);
    cvt_bf16_qk<<<4096, 256>>>(pK, pKb);

    // Approx scores (pure bf16 HMMA, K=64) chunked; rerank-topk overlaps
    cudaStreamWaitEvent(sC, eV, 0);
    for (int c = 0; c < NCHUNK; c++) {
        const long boff = (long)c * BH_PER;
        dim3 grid(T_ / 128, T_ / 128, BH_PER);
        gemm_bf16_mma<2><<<grid, 256>>>(pQb + boff * T_ * 64,
                                        pKb + boff * T_ * 64,
                                        nullptr, pSb + boff * T_ * T_,
                                        T_, 64,
                                        (long)T_ * 64, (long)T_ * 64,
                                        (long)T_ * T_);
        cudaEventRecord(eS[c], 0);
        cudaStreamWaitEvent(sC, eS[c], 0);
        topk_rerank_av<<<BH_PER * T_, 128, 0, sC>>>(pSb + boff * T_ * T_,
                                                    pQ + boff * T_ * DH_,
                                                    pK + boff * T_ * DH_,
                                                    pV + boff * T_ * DH_,
                                                    pAO, (int)boff);
    }
    cudaEventRecord(eT, sC);
    cudaStreamWaitEvent(0, eT, 0);

    // Output projection (HMMA 3-term + bias)
    split_bf16<1><<<4096, 256>>>(pAO, pAOs);
    {
        dim3 grid(D_ / 128, M / 128, 1);
        gemm_bf16_mma<1><<<grid, 256>>>(pAOs, pWos, Wo_b, out, D_, 3072, 0, 0, 0);
    }
}

// round 16
// speedup vs baseline: 1.0881x; 1.0282x over previous
#include <cuda_runtime.h>
#include <cuda_bf16.h>
#include <cstdint>

// Problem constants
#define B_  2
#define T_  2048
#define D_  1024
#define H_  16
#define DH_ 64
#define TOPK_ 32
#define BH_ (B_*H_)

// Packed fp32x2 FMA
#define FMA_F32X2(d, a, b, c) \
    asm("fma.rn.f32x2 %0, %1, %2, %3;" : "=l"(d) : "l"(a), "l"(b), "l"(c))
#define PACK_DUP_F32X2(out, v) \
    asm("mov.b64 %0, {%1, %1};" : "=l"(out) : "r"(__float_as_uint(v)))
#define UNPACK_F32X2_(lo, hi, in) \
    asm("mov.b64 {%0, %1}, %2;" : "=r"(lo), "=r"(hi) : "l"(in))

__device__ __forceinline__ uint32_t smem_u32(const void* p) {
    uint32_t a;
    asm("{ .reg .u64 t; cvta.to.shared.u64 t, %1; cvt.u32.u64 %0, t; }" : "=r"(a) : "l"(p));
    return a;
}
__device__ __forceinline__ void ldsm_x4(unsigned r[4], uint32_t addr) {
    asm volatile("ldmatrix.sync.aligned.m8n8.x4.shared.b16 {%0,%1,%2,%3}, [%4];"
        : "=r"(r[0]), "=r"(r[1]), "=r"(r[2]), "=r"(r[3]) : "r"(addr));
}
__device__ __forceinline__ void ldsm_x2(unsigned r[2], uint32_t addr) {
    asm volatile("ldmatrix.sync.aligned.m8n8.x2.shared.b16 {%0,%1}, [%2];"
        : "=r"(r[0]), "=r"(r[1]) : "r"(addr));
}
__device__ __forceinline__ void mma_bf16(float d[4], const unsigned a[4], const unsigned b[2]) {
    asm volatile("mma.sync.aligned.m16n8k16.row.col.f32.bf16.bf16.f32 "
        "{%0,%1,%2,%3}, {%4,%5,%6,%7}, {%8,%9}, {%0,%1,%2,%3};"
        : "+f"(d[0]), "+f"(d[1]), "+f"(d[2]), "+f"(d[3])
        : "r"(a[0]), "r"(a[1]), "r"(a[2]), "r"(a[3]), "r"(b[0]), "r"(b[1]));
}
__device__ __forceinline__ uint32_t stoff(int r, int g) {
    return (uint32_t)(r * 64 + ((g ^ ((r >> 1) & 3)) << 4));
}

// ---------------------------------------------------------------------------
// Scratch
// ---------------------------------------------------------------------------
__device__ __align__(16) float g_Q[(size_t)BH_ * T_ * DH_];
__device__ __align__(16) float g_K[(size_t)BH_ * T_ * DH_];
__device__ __align__(16) float g_V[(size_t)BH_ * T_ * DH_];
__device__ __align__(16) __nv_bfloat16 g_Sb[(size_t)BH_ * T_ * T_];   // approx scores
__device__ __align__(16) __nv_bfloat16 g_Xs [(size_t)4096 * 3072];  // (h,h,l)
__device__ __align__(16) __nv_bfloat16 g_AOs[(size_t)4096 * 3072];  // (h,h,l)
__device__ __align__(16) __nv_bfloat16 g_Wvs[(size_t)1024 * 3072];  // (h,l,h)
__device__ __align__(16) __nv_bfloat16 g_Wos[(size_t)1024 * 3072];  // (h,l,h)
__device__ __align__(16) __nv_bfloat16 g_Qb [(size_t)BH_ * T_ * 64];   // bf16 Q
__device__ __align__(16) __nv_bfloat16 g_Kb [(size_t)BH_ * T_ * 64];   // bf16 K

// ---------------------------------------------------------------------------
// Split: fp32 [R,1024] -> bf16 [R,3072]; AHL=1 (h,h,l), AHL=0 (h,l,h)
// ---------------------------------------------------------------------------
template<int AHL>
__global__ __launch_bounds__(256)
void split_bf16(const float* __restrict__ in, __nv_bfloat16* __restrict__ outp)
{
    const int idx = blockIdx.x * 256 + threadIdx.x;
    const int r = idx >> 8;
    const int c = (idx & 255) * 4;
    float4 v = *(const float4*)(in + (size_t)r * 1024 + c);
    __nv_bfloat162 h01 = __floats2bfloat162_rn(v.x, v.y);
    __nv_bfloat162 h23 = __floats2bfloat162_rn(v.z, v.w);
    float lx = v.x - __bfloat162float(h01.x);
    float ly = v.y - __bfloat162float(h01.y);
    float lz = v.z - __bfloat162float(h23.x);
    float lw = v.w - __bfloat162float(h23.y);
    __nv_bfloat162 l01 = __floats2bfloat162_rn(lx, ly);
    __nv_bfloat162 l23 = __floats2bfloat162_rn(lz, lw);
    __nv_bfloat162* o0 = (__nv_bfloat162*)(outp + (size_t)r * 3072 + c);
    __nv_bfloat162* o1 = (__nv_bfloat162*)(outp + (size_t)r * 3072 + 1024 + c);
    __nv_bfloat162* o2 = (__nv_bfloat162*)(outp + (size_t)r * 3072 + 2048 + c);
    o0[0] = h01; o0[1] = h23;
    if (AHL) { o1[0] = h01; o1[1] = h23; o2[0] = l01; o2[1] = l23; }
    else     { o1[0] = l01; o1[1] = l23; o2[0] = h01; o2[1] = h23; }
}

// ---------------------------------------------------------------------------
// HMMA bf16 GEMM, register-staged prefetch.
// EPI 0: head-split fp32 [BH,T,DH] (N==1024)
// EPI 1: +bias fp32 plain [M,1024]
// EPI 2: *0.125 -> bf16 plain [M,N]
// ---------------------------------------------------------------------------
template<int EPI>
__global__ __launch_bounds__(256, 2)
void gemm_bf16_mma(const __nv_bfloat16* __restrict__ Ag,
                   const __nv_bfloat16* __restrict__ Bg,
                   const float* __restrict__ bias, void* __restrict__ Cv,
                   int N, int K, long sA, long sB, long sC)
{
    const int NC = K >> 5;
    constexpr uint32_t TILE = 128 * 64;
    __shared__ __align__(128) char sm[2][2][TILE];

    const __nv_bfloat16* A = Ag + (size_t)blockIdx.z * sA;
    const __nv_bfloat16* Bm = Bg + (size_t)blockIdx.z * sB;

    const int tid = threadIdx.x, lane = tid & 31, wid = tid >> 5;
    const int wr = wid >> 2, wc = wid & 3;
    const int m0 = blockIdx.y * 128, n0 = blockIdx.x * 128;
    const uint32_t sbase = smem_u32(&sm[0][0][0]);

    float acc[4][4][4];
#pragma unroll
    for (int mb = 0; mb < 4; mb++)
#pragma unroll
        for (int nb = 0; nb < 4; nb++)
#pragma unroll
            for (int e = 0; e < 4; e++) acc[mb][nb][e] = 0.f;

    const int aRow = (lane & 15), aG = (lane >> 4) & 1;
    const int bRow = (lane & 7),  bG = (lane >> 3) & 1;

    const int lr0 = (tid * 2) >> 2,      lg0 = (tid * 2) & 3;
    const int lr1 = (tid * 2 + 1) >> 2,  lg1 = (tid * 2 + 1) & 3;

    {
        *(uint4*)(&sm[0][0][0] + stoff(lr0, lg0)) = *(const uint4*)(A  + (size_t)(m0 + lr0) * K + lg0 * 8);
        *(uint4*)(&sm[0][0][0] + stoff(lr1, lg1)) = *(const uint4*)(A  + (size_t)(m0 + lr1) * K + lg1 * 8);
        *(uint4*)(&sm[0][1][0] + stoff(lr0, lg0)) = *(const uint4*)(Bm + (size_t)(n0 + lr0) * K + lg0 * 8);
        *(uint4*)(&sm[0][1][0] + stoff(lr1, lg1)) = *(const uint4*)(Bm + (size_t)(n0 + lr1) * K + lg1 * 8);
    }
    __syncthreads();

    for (int c = 0; c < NC; c++) {
        const int buf = c & 1;
        uint4 va0, va1, vb0, vb1;
        const bool pf = (c + 1 < NC);
        if (pf) {
            const int ks = (c + 1) * 32;
            va0 = *(const uint4*)(A  + (size_t)(m0 + lr0) * K + ks + lg0 * 8);
            va1 = *(const uint4*)(A  + (size_t)(m0 + lr1) * K + ks + lg1 * 8);
            vb0 = *(const uint4*)(Bm + (size_t)(n0 + lr0) * K + ks + lg0 * 8);
            vb1 = *(const uint4*)(Bm + (size_t)(n0 + lr1) * K + ks + lg1 * 8);
        }
        const uint32_t Ab = sbase + (uint32_t)buf * (2 * TILE);
        const uint32_t Bb = Ab + TILE;
#pragma unroll
        for (int s16 = 0; s16 < 2; s16++) {
            unsigned bfr[4][2];
#pragma unroll
            for (int nb = 0; nb < 4; nb++) {
                int r = 32 * wc + 8 * nb + bRow;
                ldsm_x2(bfr[nb], Bb + stoff(r, s16 * 2 + bG));
            }
#pragma unroll
            for (int mb = 0; mb < 4; mb++) {
                unsigned af[4];
                int r = 64 * wr + 16 * mb + aRow;
                ldsm_x4(af, Ab + stoff(r, s16 * 2 + aG));
#pragma unroll
                for (int nb = 0; nb < 4; nb++)
                    mma_bf16(acc[mb][nb], af, bfr[nb]);
            }
        }
        if (pf) {
            const int nb_ = buf ^ 1;
            *(uint4*)(&sm[nb_][0][0] + stoff(lr0, lg0)) = va0;
            *(uint4*)(&sm[nb_][0][0] + stoff(lr1, lg1)) = va1;
            *(uint4*)(&sm[nb_][1][0] + stoff(lr0, lg0)) = vb0;
            *(uint4*)(&sm[nb_][1][0] + stoff(lr1, lg1)) = vb1;
        }
        __syncthreads();
    }

#pragma unroll
    for (int mb = 0; mb < 4; mb++) {
        const int mlo = m0 + 64 * wr + 16 * mb + (lane >> 2);
#pragma unroll
        for (int nb = 0; nb < 4; nb++) {
            const int n = n0 + 32 * wc + 8 * nb + (lane & 3) * 2;
            float2 lo = make_float2(acc[mb][nb][0], acc[mb][nb][1]);
            float2 hi = make_float2(acc[mb][nb][2], acc[mb][nb][3]);
            if (EPI == 1) {
                float* C = (float*)Cv;
                float bx = bias[n], by = bias[n + 1];
                lo.x += bx; lo.y += by; hi.x += bx; hi.y += by;
                *(float2*)(C + (size_t)mlo * N + n) = lo;
                *(float2*)(C + (size_t)(mlo + 8) * N + n) = hi;
            } else if (EPI == 2) {
                __nv_bfloat16* C = (__nv_bfloat16*)Cv + (size_t)blockIdx.z * sC;
                __nv_bfloat162 p0 = __floats2bfloat162_rn(lo.x * 0.125f, lo.y * 0.125f);
                __nv_bfloat162 p1 = __floats2bfloat162_rn(hi.x * 0.125f, hi.y * 0.125f);
                *(__nv_bfloat162*)(C + (size_t)mlo * N + n) = p0;
                *(__nv_bfloat162*)(C + (size_t)(mlo + 8) * N + n) = p1;
            } else {
                float* C = (float*)Cv;
                const int h = n >> 6, inner = n & 63;
                const int bb0 = mlo >> 11, t0v = mlo & (T_ - 1);
                const int bb1 = (mlo + 8) >> 11, t1v = (mlo + 8) & (T_ - 1);
                *(float2*)(C + (((size_t)(bb0 * H_ + h) * T_ + t0v) * DH_ + inner)) = lo;
                *(float2*)(C + (((size_t)(bb1 * H_ + h) * T_ + t1v) * DH_ + inner)) = hi;
            }
        }
    }
}

// ---------------------------------------------------------------------------
// SIMT FFMA2 GEMM — Q/K projection, half-N (512 cols = 8 heads), head-split
// epilogue writing fp32 AND bf16 copies. Accumulation bit-identical to R8.
// ---------------------------------------------------------------------------
__global__ __launch_bounds__(256)
void gemm_abt_heads(const float* __restrict__ A, const float* __restrict__ Bm,
                    float* __restrict__ Cf, __nv_bfloat16* __restrict__ Cb,
                    int M, int K, int h_base)
{
    __shared__ __align__(16) float AsT[16][128];
    __shared__ __align__(16) float BsT[16][128];

    const int tid = threadIdx.x;
    const int tx = tid & 15;
    const int ty = tid >> 4;
    const int m0 = blockIdx.y * 128;
    const int n0 = blockIdx.x * 128;

    unsigned long long acc2[8][4];
#pragma unroll
    for (int i = 0; i < 8; i++)
#pragma unroll
        for (int j = 0; j < 4; j++) acc2[i][j] = 0ull;

    for (int k0 = 0; k0 < K; k0 += 16) {
#pragma unroll
        for (int i = 0; i < 2; i++) {
            int idx  = tid * 2 + i;
            int row  = idx >> 2;
            int col4 = (idx & 3) * 4;
            float4 va = *(const float4*)(A + (long)(m0 + row) * K + k0 + col4);
            AsT[col4 + 0][row] = va.x;
            AsT[col4 + 1][row] = va.y;
            AsT[col4 + 2][row] = va.z;
            AsT[col4 + 3][row] = va.w;
            float4 vb = *(const float4*)(Bm + (long)(n0 + row) * K + k0 + col4);
            BsT[col4 + 0][row] = vb.x;
            BsT[col4 + 1][row] = vb.y;
            BsT[col4 + 2][row] = vb.z;
            BsT[col4 + 3][row] = vb.w;
        }
        __syncthreads();
#pragma unroll
        for (int k = 0; k < 16; k++) {
            float a[8];
            *(float4*)&a[0] = *(const float4*)&AsT[k][ty * 8];
            *(float4*)&a[4] = *(const float4*)&AsT[k][ty * 8 + 4];
            ulonglong2 b01 = *(const ulonglong2*)&BsT[k][tx * 8];
            ulonglong2 b23 = *(const ulonglong2*)&BsT[k][tx * 8 + 4];
#pragma unroll
            for (int i = 0; i < 8; i++) {
                unsigned long long ad;
                PACK_DUP_F32X2(ad, a[i]);
                FMA_F32X2(acc2[i][0], ad, b01.x, acc2[i][0]);
                FMA_F32X2(acc2[i][1], ad, b01.y, acc2[i][1]);
                FMA_F32X2(acc2[i][2], ad, b23.x, acc2[i][2]);
                FMA_F32X2(acc2[i][3], ad, b23.y, acc2[i][3]);
            }
        }
        __syncthreads();
    }

#pragma unroll
    for (int i = 0; i < 8; i++) {
        int m = m0 + ty * 8 + i;
        int bb = m >> 11, t = m & (T_ - 1);
#pragma unroll
        for (int jp = 0; jp < 4; jp += 2) {
            int n = n0 + tx * 8 + jp * 2;
            unsigned r0, r1, r2, r3;
            UNPACK_F32X2_(r0, r1, acc2[i][jp]);
            UNPACK_F32X2_(r2, r3, acc2[i][jp + 1]);
            float4 r = make_float4(__uint_as_float(r0), __uint_as_float(r1),
                                   __uint_as_float(r2), __uint_as_float(r3));
            int h = (n >> 6) + h_base, inner = n & (DH_ - 1);
            size_t off = ((size_t)(bb * H_ + h) * T_ + t) * DH_ + inner;
            *(float4*)(Cf + off) = r;
            __nv_bfloat162 p0 = __floats2bfloat162_rn(r.x, r.y);
            __nv_bfloat162 p1 = __floats2bfloat162_rn(r.z, r.w);
            __nv_bfloat162* db = (__nv_bfloat162*)(Cb + off);
            db[0] = p0; db[1] = p1;
        }
    }
}

// ---------------------------------------------------------------------------
// Approx-select (16-bit radix on bf16 scores) + exact fp32 re-rank +
// softmax + sparse AV, writing (h,h,l) bf16 split output directly.
// ---------------------------------------------------------------------------
__device__ __forceinline__ int enc16(int b) {
    return (b & 0x8000) ? (~b & 0xFFFF) : (b | 0x8000);
}
__device__ __forceinline__ float dec16f(int u) {
    int b = (u & 0x8000) ? (u & 0x7FFF) : (~u & 0xFFFF);
    return __uint_as_float((unsigned)b << 16);
}

__global__ __launch_bounds__(128)
void topk_rerank_av(const __nv_bfloat16* __restrict__ S,
                    const float* __restrict__ Qf, const float* __restrict__ Kf,
                    const float* __restrict__ V, __nv_bfloat16* __restrict__ AOs,
                    int bh_base)
{
    __shared__ int      hist[256];
    __shared__ float    s_q[64];
    __shared__ int      s_list[128];
    __shared__ float    s_v[128];
    __shared__ float    s_p[128];
    __shared__ float    s_part[128];
    __shared__ int      s_prefix;
    __shared__ int      s_kp;
    __shared__ int      s_cnt;
    __shared__ float    s_inv;

    const long row = blockIdx.x;
    const int bhl = (int)(row >> 11);
    const int bh = bh_base + bhl;
    const int tq = (int)(row & (T_ - 1));
    const int tid = threadIdx.x;

    if (tid == 0) s_cnt = 0;
    if (tid < 16)
        *(float4*)&s_q[tid * 4] =
            *(const float4*)(Qf + (((size_t)bhl * T_ + tq) * DH_) + tid * 4);

    const uint4* S4 = (const uint4*)(S + row * T_);
    int us[16];
    int ibase[2];
#pragma unroll
    for (int i = 0; i < 2; i++) {
        uint4 w = S4[tid + i * 128];
        ibase[i] = (tid + i * 128) * 8;
        unsigned ws[4] = {w.x, w.y, w.z, w.w};
#pragma unroll
        for (int j = 0; j < 4; j++) {
            us[i * 8 + j * 2 + 0] = enc16((int)(ws[j] & 0xFFFFu));
            us[i * 8 + j * 2 + 1] = enc16((int)(ws[j] >> 16));
        }
    }

    // 2-level radix select (exact kth largest of bf16 values, k=32)
    int prefix = 0, kprime = TOPK_;
#pragma unroll
    for (int level = 1; level >= 0; --level) {
        const int sh = level * 8;
        hist[tid] = 0;
        hist[tid + 128] = 0;
        __syncthreads();
        const int hip = prefix >> (sh + 8);
#pragma unroll
        for (int i = 0; i < 16; i++) {
            int u = us[i];
            if ((u >> (sh + 8)) == hip)
                atomicAdd(&hist[(u >> sh) & 0xFF], 1);
        }
        __syncthreads();
        if (tid < 32) {
            const int base = tid * 8;
            int s = 0;
#pragma unroll
            for (int j = 0; j < 8; j++) s += hist[base + j];
            int suf = s;
#pragma unroll
            for (int off = 1; off < 32; off <<= 1) {
                int o = __shfl_down_sync(0xffffffffu, suf, off);
                if (tid + off < 32) suf += o;
            }
            int sufnext = __shfl_down_sync(0xffffffffu, suf, 1);
            if (tid == 31) sufnext = 0;
            unsigned mk = __ballot_sync(0xffffffffu, suf >= kprime);
            int lsel = 31 - __clz(mk);
            if (tid == lsel) {
                int running = sufnext;
                int b = base + 7;
                for (; b >= base; --b) {
                    int h = hist[b];
                    if (running + h >= kprime) break;
                    running += h;
                }
                s_prefix = prefix | (b << sh);
                s_kp = kprime - running;
            }
        }
        __syncthreads();
        prefix = s_prefix;
        kprime = s_kp;
    }

    const float thrf = dec16f(prefix) - 0.12f;
    const int uthr_w = enc16((int)(__bfloat16_as_ushort(__float2bfloat16(thrf))));

#pragma unroll
    for (int i = 0; i < 16; i++) {
        if (us[i] >= uthr_w) {
            int pos = atomicAdd(&s_cnt, 1);
            if (pos < 128)
                s_list[pos] = ibase[i >> 3] + (i & 7);
        }
    }
    __syncthreads();
    const int cnt = min(s_cnt, 128);

    // exact fp32 recompute for candidates
    if (tid < cnt) {
        const float* Kr = Kf + ((size_t)bhl * T_ + s_list[tid]) * DH_;
        float acc = 0.f;
#pragma unroll
        for (int k4 = 0; k4 < 16; k4++) {
            float4 kv = *(const float4*)(Kr + k4 * 4);
            acc = fmaf(s_q[k4 * 4 + 0], kv.x, acc);
            acc = fmaf(s_q[k4 * 4 + 1], kv.y, acc);
            acc = fmaf(s_q[k4 * 4 + 2], kv.z, acc);
            acc = fmaf(s_q[k4 * 4 + 3], kv.w, acc);
        }
        s_v[tid] = acc * 0.125f;
    }
    __syncthreads();

    float m = -3.4e38f;
    for (int j = 0; j < cnt; j++) m = fmaxf(m, s_v[j]);
    if (tid < cnt) {
        const float v = s_v[tid];
        int c = 0;
        for (int j = 0; j < cnt; j++) c += (s_v[j] > v);
        s_p[tid] = (c < TOPK_) ? __expf(v - m) : 0.f;
    }
    __syncthreads();

    if (tid < 32) {
        float sum = 0.f;
        for (int e = tid; e < cnt; e += 32) sum += s_p[e];
#pragma unroll
        for (int off = 16; off; off >>= 1)
            sum += __shfl_xor_sync(0xffffffffu, sum, off);
        if (tid == 0) s_inv = 1.f / sum;
    }
    __syncthreads();

    {
        const int dim = tid & 63;
        const int half = tid >> 6;
        const float* Vb = V + (size_t)bhl * T_ * DH_;
        float acc = 0.f;
        for (int e = half; e < cnt; e += 2)
            acc += s_p[e] * Vb[(size_t)s_list[e] * DH_ + dim];
        s_part[tid] = acc;
    }
    __syncthreads();
    if (tid < DH_) {
        const int bb = bh >> 4, h = bh & (H_ - 1);
        float o = (s_part[tid] + s_part[tid + 64]) * s_inv;
        // write (h,h,l) bf16 split of AO directly
        __nv_bfloat16 hb = __float2bfloat16(o);
        __nv_bfloat16 lb = __float2bfloat16(o - __bfloat162float(hb));
        __nv_bfloat16* base = AOs + ((size_t)(bb * T_ + tq)) * 3072 + h * DH_ + tid;
        base[0] = hb;
        base[1024] = hb;
        base[2048] = lb;
    }
}

// ---------------------------------------------------------------------------
// Launch — QK proj chunked over head halves; scores/topk tail-fill.
// ---------------------------------------------------------------------------
extern "C" void kernel_launch(void* const* d_in, const int* in_sizes, int n_in,
                              void* d_out, int out_size)
{
    const float* x    = (const float*)d_in[0];
    const float* Wq   = (const float*)d_in[1];
    const float* Wk   = (const float*)d_in[2];
    const float* Wv   = (const float*)d_in[3];
    const float* Wo_w = (const float*)d_in[4];
    const float* Wo_b = (const float*)d_in[5];
    float* out = (float*)d_out;

    float *pQ, *pK, *pV;
    __nv_bfloat16 *pSb, *pXs, *pAOs, *pWvs, *pWos, *pQb, *pKb;
    cudaGetSymbolAddress((void**)&pQ,   g_Q);
    cudaGetSymbolAddress((void**)&pK,   g_K);
    cudaGetSymbolAddress((void**)&pV,   g_V);
    cudaGetSymbolAddress((void**)&pSb,  g_Sb);
    cudaGetSymbolAddress((void**)&pXs,  g_Xs);
    cudaGetSymbolAddress((void**)&pAOs, g_AOs);
    cudaGetSymbolAddress((void**)&pWvs, g_Wvs);
    cudaGetSymbolAddress((void**)&pWos, g_Wos);
    cudaGetSymbolAddress((void**)&pQb,  g_Qb);
    cudaGetSymbolAddress((void**)&pKb,  g_Kb);

    static cudaStream_t sB = nullptr, sC = nullptr, sK = nullptr;
    static cudaEvent_t e0, eV, eQ[2], eK[2], eT;
    if (!sB) {
        cudaStreamCreateWithFlags(&sB, cudaStreamNonBlocking);
        cudaStreamCreateWithFlags(&sC, cudaStreamNonBlocking);
        cudaStreamCreateWithFlags(&sK, cudaStreamNonBlocking);
        cudaEventCreateWithFlags(&e0, cudaEventDisableTiming);
        cudaEventCreateWithFlags(&eV, cudaEventDisableTiming);
        for (int i = 0; i < 2; i++) {
            cudaEventCreateWithFlags(&eQ[i], cudaEventDisableTiming);
            cudaEventCreateWithFlags(&eK[i], cudaEventDisableTiming);
        }
        cudaEventCreateWithFlags(&eT, cudaEventDisableTiming);
    }

    const int M = B_ * T_;   // 4096

    cudaEventRecord(e0, 0);
    cudaStreamWaitEvent(sB, e0, 0);
    cudaStreamWaitEvent(sK, e0, 0);

    // Stream B: splits + V projection (tensor pipe)
    split_bf16<1><<<4096, 256, 0, sB>>>(x, pXs);
    split_bf16<0><<<1024, 256, 0, sB>>>(Wv, pWvs);
    split_bf16<0><<<1024, 256, 0, sB>>>(Wo_w, pWos);
    {
        dim3 grid(D_ / 128, M / 128, 1);
        gemm_bf16_mma<0><<<grid, 256, 0, sB>>>(pXs, pWvs, nullptr, pV, D_, 3072, 0, 0, 0);
    }
    cudaEventRecord(eV, sB);

    // Q halves on main stream, K halves on sK (concurrent: 128+128 CTAs/pair)
    for (int hb = 0; hb < 2; hb++) {
        dim3 grid(4, M / 128, 1);   // N=512
        gemm_abt_heads<<<grid, 256, 0, 0>>>(x, Wq + (size_t)hb * 512 * 1024,
                                            pQ, pQb, M, D_, hb * 8);
        cudaEventRecord(eQ[hb], 0);
        gemm_abt_heads<<<grid, 256, 0, sK>>>(x, Wk + (size_t)hb * 512 * 1024,
                                             pK, pKb, M, D_, hb * 8);
        cudaEventRecord(eK[hb], sK);
    }

    // Stream C: per half-head-group scores + rerank-topk
    cudaStreamWaitEvent(sC, eV, 0);
    for (int hb = 0; hb < 2; hb++) {
        cudaStreamWaitEvent(sC, eQ[hb], 0);
        cudaStreamWaitEvent(sC, eK[hb], 0);
        for (int b = 0; b < 2; b++) {
            const long bh0 = (long)b * 16 + hb * 8;
            dim3 g(T_ / 128, T_ / 128, 8);
            gemm_bf16_mma<2><<<g, 256, 0, sC>>>(pQb + bh0 * T_ * 64,
                                                pKb + bh0 * T_ * 64,
                                                nullptr, pSb + bh0 * T_ * T_,
                                                T_, 64,
                                                (long)T_ * 64, (long)T_ * 64,
                                                (long)T_ * T_);
            topk_rerank_av<<<8 * T_, 128, 0, sC>>>(pSb + bh0 * T_ * T_,
                                                   pQ + bh0 * T_ * DH_,
                                                   pK + bh0 * T_ * DH_,
                                                   pV + bh0 * T_ * DH_,
                                                   pAOs, (int)bh0);
        }
    }
    cudaEventRecord(eT, sC);
    cudaStreamWaitEvent(0, eT, 0);

    // Output projection (HMMA 3-term + bias) — AOs written directly by topk
    {
        dim3 grid(D_ / 128, M / 128, 1);
        gemm_bf16_mma<1><<<grid, 256>>>(pAOs, pWos, Wo_b, out, D_, 3072, 0, 0, 0);
    }
}